// round 14
// baseline (speedup 1.0000x reference)
#include <cuda_runtime.h>
#include <cuda_fp16.h>
#include <stdint.h>
#include <math.h>

// Shapes: B=2, Tq=2048, Tctx=2048 -> Tk=4096, D=1024, H=16, hd=64
#define GK 1024
#define GN 1024

// ---------------- persistent fp16 scratch ----------------
__device__ __half g_xh[4194304];            // x fp16    [4096][1024]
__device__ __half g_ch[4194304];            // ctx fp16  [4096][1024]
__device__ __half g_Wt[6][1048576];         // W^T fp16  [1024 n][1024 k]
__device__ __half g_Qh[4194304];            // Q (scaled)[2*2048][1024]
__device__ __half g_Kh[8388608];            // K concat  [2*4096][1024]
__device__ __half g_Vh[8388608];            // V concat  [2*4096][1024]
__device__ __half g_Oh[4194304];            // attn out  [2*2048][1024]

// ---------------- ptx helpers ----------------
__device__ __forceinline__ uint32_t smem_u32(const void* p) {
    return static_cast<uint32_t>(__cvta_generic_to_shared(p));
}
__device__ __forceinline__ void cp16(uint32_t dst, const void* src) {
    asm volatile("cp.async.cg.shared.global [%0], [%1], 16;" :: "r"(dst), "l"(src));
}
__device__ __forceinline__ void cp_commit() {
    asm volatile("cp.async.commit_group;" ::: "memory");
}
__device__ __forceinline__ void cp_wait1() {
    asm volatile("cp.async.wait_group 1;" ::: "memory");
}
__device__ __forceinline__ void cp_wait0() {
    asm volatile("cp.async.wait_group 0;" ::: "memory");
}
__device__ __forceinline__ void ldsm_x4(uint32_t* r, uint32_t addr) {
    asm volatile("ldmatrix.sync.aligned.m8n8.x4.shared.b16 {%0,%1,%2,%3}, [%4];"
                 : "=r"(r[0]), "=r"(r[1]), "=r"(r[2]), "=r"(r[3]) : "r"(addr));
}
__device__ __forceinline__ void ldsm_x4t(uint32_t* r, uint32_t addr) {
    asm volatile("ldmatrix.sync.aligned.m8n8.x4.trans.shared.b16 {%0,%1,%2,%3}, [%4];"
                 : "=r"(r[0]), "=r"(r[1]), "=r"(r[2]), "=r"(r[3]) : "r"(addr));
}
__device__ __forceinline__ void mma16816(float* c, const uint32_t* a, const uint32_t* b) {
    asm volatile(
        "mma.sync.aligned.m16n8k16.row.col.f32.f16.f16.f32 "
        "{%0,%1,%2,%3}, {%4,%5,%6,%7}, {%8,%9}, {%0,%1,%2,%3};"
        : "+f"(c[0]), "+f"(c[1]), "+f"(c[2]), "+f"(c[3])
        : "r"(a[0]), "r"(a[1]), "r"(a[2]), "r"(a[3]), "r"(b[0]), "r"(b[1]));
}
__device__ __forceinline__ uint32_t pack_h2(float lo, float hi) {
    __half2 h;
    h.x = __float2half_rn(lo);
    h.y = __float2half_rn(hi);
    uint32_t u;
    memcpy(&u, &h, 4);
    return u;
}
__device__ __forceinline__ uint32_t h2exp2(uint32_t x) {
    uint32_t r;
    asm volatile("ex2.approx.f16x2 %0, %1;" : "=r"(r) : "r"(x));
    return r;
}

// ---------------- fused fp32 -> fp16 convert (z selects tensor) ----------
__global__ void f2h2_kernel(const float* __restrict__ in0, const float* __restrict__ in1,
                            __half* __restrict__ out0, __half* __restrict__ out1, int n4) {
    const float* in = blockIdx.z ? in1 : in0;
    __half* out = blockIdx.z ? out1 : out0;
    int i = blockIdx.x * blockDim.x + threadIdx.x;
    if (i < n4) {
        float4 v = reinterpret_cast<const float4*>(in)[i];
        __half2 a; a.x = __float2half_rn(v.x); a.y = __float2half_rn(v.y);
        __half2 b; b.x = __float2half_rn(v.z); b.y = __float2half_rn(v.w);
        reinterpret_cast<__half2*>(out)[i * 2]     = a;
        reinterpret_cast<__half2*>(out)[i * 2 + 1] = b;
    }
}

// ---------------- fused W [K][N] fp32 -> Wt [N][K] fp16 (z = weight idx) ----
__global__ void wtrans6_kernel(const float* w0, const float* w1, const float* w2,
                               const float* w3, const float* w4, const float* w5,
                               __half* __restrict__ WtBase) {
    __shared__ float t[32][33];
    const float* W;
    switch (blockIdx.z) {
        case 0: W = w0; break;
        case 1: W = w1; break;
        case 2: W = w2; break;
        case 3: W = w3; break;
        case 4: W = w4; break;
        default: W = w5; break;
    }
    __half* Wt = WtBase + (size_t)blockIdx.z * 1048576u;
    int n0 = blockIdx.x * 32, k0 = blockIdx.y * 32;
    int tx = threadIdx.x, ty = threadIdx.y;
#pragma unroll
    for (int i = 0; i < 32; i += 8)
        t[ty + i][tx] = W[(size_t)(k0 + ty + i) * GN + n0 + tx];
    __syncthreads();
#pragma unroll
    for (int i = 0; i < 32; i += 8)
        Wt[(size_t)(n0 + ty + i) * GK + k0 + tx] = __float2half_rn(t[tx][ty + i]);
}

// ---------------- HMMA GEMM, 3-stage cp.async pipeline (R10 proven) --------
// 512 threads, 16 warps (4m x 4n), warp tile 32x32, CTA tile 128x128, BK=32.
#define TSZ 10240
#define A_OFF(s) ((s) * TSZ)
#define B_OFF(s) (3 * TSZ + (s) * TSZ)
#define SM_GEMM (6 * TSZ)

__device__ __forceinline__ void hgemm_body(
    const __half* __restrict__ A, const __half* __restrict__ Bt,
    const float* __restrict__ bias, __half* __restrict__ outH,
    float* __restrict__ outF, int f32out, int bstride, int roff, float scale,
    char* smem)
{
    const uint32_t sb = smem_u32(smem);
    const int tid = threadIdx.x;
    const int lane = tid & 31;
    const int wid = tid >> 5;
    const int wm = (wid >> 2) * 32;
    const int wn = (wid & 3) * 32;
    const int row0 = blockIdx.y * 128;
    const int col0 = blockIdx.x * 128;

    const __half* Ag = A + (size_t)row0 * GK;
    const __half* Bg = Bt + (size_t)col0 * GK;

#define GLOAD(kc, s)                                                         \
    {                                                                        \
        int r = tid >> 2;                                                    \
        int cb = (tid & 3) * 8;                                              \
        cp16(sb + A_OFF(s) + r * 80 + cb * 2,                                \
             Ag + (size_t)r * GK + (kc) * 32 + cb);                          \
        cp16(sb + B_OFF(s) + r * 80 + cb * 2,                                \
             Bg + (size_t)r * GK + (kc) * 32 + cb);                          \
    }

    float acc[2][4][4];
#pragma unroll
    for (int i = 0; i < 2; i++)
#pragma unroll
        for (int j = 0; j < 4; j++)
#pragma unroll
            for (int k = 0; k < 4; k++) acc[i][j][k] = 0.f;

    GLOAD(0, 0); cp_commit();
    GLOAD(1, 1); cp_commit();

    const int mat = lane >> 3;
    const int mrow = lane & 7;

    for (int c = 0; c < 32; c++) {
        const int s = c % 3;
        cp_wait1();
        __syncthreads();
        if (c + 2 < 32) GLOAD(c + 2, (c + 2) % 3);
        cp_commit();

#pragma unroll
        for (int ks = 0; ks < 2; ks++) {
            uint32_t af[2][4];
#pragma unroll
            for (int mt = 0; mt < 2; mt++) {
                int row = wm + mt * 16 + (lane & 7) + (lane & 8);
                int col = ks * 16 + (lane >> 4) * 8;
                ldsm_x4(af[mt], sb + A_OFF(s) + (row * 40 + col) * 2);
            }
            uint32_t bf[4][2];
#pragma unroll
            for (int np = 0; np < 2; np++) {
                int row = wn + (np * 2 + (mat >> 1)) * 8 + mrow;
                int col = ks * 16 + (mat & 1) * 8;
                uint32_t r4[4];
                ldsm_x4(r4, sb + B_OFF(s) + (row * 40 + col) * 2);
                bf[np * 2][0] = r4[0];     bf[np * 2][1] = r4[1];
                bf[np * 2 + 1][0] = r4[2]; bf[np * 2 + 1][1] = r4[3];
            }
#pragma unroll
            for (int mt = 0; mt < 2; mt++)
#pragma unroll
                for (int nt = 0; nt < 4; nt++)
                    mma16816(acc[mt][nt], af[mt], bf[nt]);
        }
    }

    const int g = lane >> 2;
    const int qd = lane & 3;
#pragma unroll
    for (int mt = 0; mt < 2; mt++) {
        int r0 = row0 + wm + mt * 16 + g;
        int r1 = r0 + 8;
        size_t or0 = (size_t)((r0 >> 11) * bstride + (r0 & 2047) + roff);
        size_t or1 = (size_t)((r1 >> 11) * bstride + (r1 & 2047) + roff);
#pragma unroll
        for (int nt = 0; nt < 4; nt++) {
            int col = col0 + wn + nt * 8 + qd * 2;
            float b0 = bias[col];
            float b1 = bias[col + 1];
            float v00 = (acc[mt][nt][0] + b0) * scale;
            float v01 = (acc[mt][nt][1] + b1) * scale;
            float v10 = (acc[mt][nt][2] + b0) * scale;
            float v11 = (acc[mt][nt][3] + b1) * scale;
            if (f32out) {
                outF[or0 * GN + col]     = v00;
                outF[or0 * GN + col + 1] = v01;
                outF[or1 * GN + col]     = v10;
                outF[or1 * GN + col + 1] = v11;
            } else {
                *reinterpret_cast<uint32_t*>(&outH[or0 * GN + col]) = pack_h2(v00, v01);
                *reinterpret_cast<uint32_t*>(&outH[or1 * GN + col]) = pack_h2(v10, v11);
            }
        }
    }
}

__global__ __launch_bounds__(512, 2) void hgemm5_kernel(
    const __half* __restrict__ xh, const __half* __restrict__ ch,
    const __half* __restrict__ WtBase,
    const float* __restrict__ b0, const float* __restrict__ b1,
    const float* __restrict__ b2, const float* __restrict__ b3,
    const float* __restrict__ b4,
    __half* __restrict__ Qh, __half* __restrict__ Kh, __half* __restrict__ Vh,
    float qscale)
{
    extern __shared__ char smem[];
    switch (blockIdx.z) {
        case 0:
            hgemm_body(xh, WtBase + 0u * 1048576u, b0, Qh, nullptr, 0, 2048, 0, qscale, smem);
            break;
        case 1:
            hgemm_body(xh, WtBase + 1u * 1048576u, b1, Kh, nullptr, 0, 4096, 0, 1.0f, smem);
            break;
        case 2:
            hgemm_body(ch, WtBase + 3u * 1048576u, b3, Kh, nullptr, 0, 4096, 2048, 1.0f, smem);
            break;
        case 3:
            hgemm_body(xh, WtBase + 2u * 1048576u, b2, Vh, nullptr, 0, 4096, 0, 1.0f, smem);
            break;
        default:
            hgemm_body(ch, WtBase + 4u * 1048576u, b4, Vh, nullptr, 0, 4096, 2048, 1.0f, smem);
            break;
    }
}

__global__ __launch_bounds__(512, 2) void hgemm_kernel(
    const __half* __restrict__ A, const __half* __restrict__ Bt,
    const float* __restrict__ bias, __half* __restrict__ outH,
    float* __restrict__ outF, int f32out, int bstride, int roff, float scale)
{
    extern __shared__ char smem[];
    hgemm_body(A, Bt, bias, outH, outF, f32out, bstride, roff, scale, smem);
}

// ---------------- flash attention (HMMA) — R10 math, 4-stage ring ----------
// Barrier every 2 iterations: with a 4-deep ring the overwrite distance is 3,
// so one __syncthreads per 2 kb suffices. Warps may drift by a full iteration,
// interleaving softmax (ALU/MUFU) of one warp with MMAs of another.
#define KVSTG 18432
#define KOFF(s) ((s) * KVSTG)
#define VOFF(s) ((s) * KVSTG + 9216)
#define SM_ATTN (4 * KVSTG)               // 73728 B

__global__ __launch_bounds__(256, 2) void attn_hmma_kernel(
    const __half* __restrict__ Q, const __half* __restrict__ K,
    const __half* __restrict__ V, __half* __restrict__ O)
{
    extern __shared__ char smem[];
    const uint32_t sb = smem_u32(smem);

    const int tid = threadIdx.x;
    const int lane = tid & 31;
    const int wid = tid >> 5;
    const int qt = blockIdx.x;
    const int h = blockIdx.y;
    const int b = blockIdx.z;
    const int q0 = qt * 128 + wid * 16;
    const int g = lane >> 2;
    const int qd = lane & 3;
    const int mat = lane >> 3;
    const int mrow = lane & 7;

    const __half* Qb = Q + ((size_t)b * 2048 + q0) * GN + h * 64;
    const __half* Kb = K + (size_t)b * 4096 * GN + h * 64;
    const __half* Vb = V + (size_t)b * 4096 * GN + h * 64;

    uint32_t qf[4][4];
#pragma unroll
    for (int ks = 0; ks < 4; ks++) {
        int c0 = ks * 16 + qd * 2;
        qf[ks][0] = *reinterpret_cast<const uint32_t*>(Qb + (size_t)g * GN + c0);
        qf[ks][1] = *reinterpret_cast<const uint32_t*>(Qb + (size_t)(g + 8) * GN + c0);
        qf[ks][2] = *reinterpret_cast<const uint32_t*>(Qb + (size_t)g * GN + c0 + 8);
        qf[ks][3] = *reinterpret_cast<const uint32_t*>(Qb + (size_t)(g + 8) * GN + c0 + 8);
    }

    float of[8][4];
#pragma unroll
    for (int i = 0; i < 8; i++)
#pragma unroll
        for (int j = 0; j < 4; j++) of[i][j] = 0.f;
    float ls[4] = {0.f, 0.f, 0.f, 0.f};
    float m0 = -1e30f, m1 = -1e30f;

    const uint32_t ONES2 = 0x3C003C00u;
    const uint32_t onesb[2] = {ONES2, ONES2};

    const int lr = tid & 63;
    const int lc = (tid >> 6) * 16;

#define LOAD_KV(kb, s)                                                       \
    {                                                                        \
        const __half* Kg = Kb + (size_t)((kb) * 64 + lr) * GN + lc;          \
        const __half* Vg = Vb + (size_t)((kb) * 64 + lr) * GN + lc;          \
        cp16(sb + KOFF(s) + (lr * 72 + lc) * 2, Kg);                         \
        cp16(sb + KOFF(s) + (lr * 72 + lc + 8) * 2, Kg + 8);                 \
        cp16(sb + VOFF(s) + (lr * 72 + lc) * 2, Vg);                         \
        cp16(sb + VOFF(s) + (lr * 72 + lc + 8) * 2, Vg + 8);                 \
    }

    LOAD_KV(0, 0); cp_commit();
    LOAD_KV(1, 1); cp_commit();

    for (int kb2 = 0; kb2 < 64; kb2 += 2) {
        cp_wait0();          // stages kb2, kb2+1 loaded
        __syncthreads();     // visible to all warps; stages (kb2+2)&3, (kb2+3)&3 free

#pragma unroll
        for (int sub = 0; sub < 2; sub++) {
            const int kb = kb2 + sub;
            const int s = kb & 3;

            if (kb + 2 < 64) LOAD_KV(kb + 2, (kb + 2) & 3);
            cp_commit();

            const uint32_t sK = sb + KOFF(s);
            const uint32_t sV = sb + VOFF(s);

            // S = Qs @ K^T : x4 loads fragment pairs (nt, nt+1)
            float sc[8][4];
#pragma unroll
            for (int nt = 0; nt < 8; nt++) {
                sc[nt][0] = 0.f; sc[nt][1] = 0.f; sc[nt][2] = 0.f; sc[nt][3] = 0.f;
            }
#pragma unroll
            for (int ks = 0; ks < 4; ks++) {
                uint32_t bf[8][2];
#pragma unroll
                for (int np = 0; np < 4; np++) {
                    int row = (np * 2 + (mat >> 1)) * 8 + mrow;
                    int col = ks * 16 + (mat & 1) * 8;
                    uint32_t r4[4];
                    ldsm_x4(r4, sK + (row * 72 + col) * 2);
                    bf[np * 2][0] = r4[0];     bf[np * 2][1] = r4[1];
                    bf[np * 2 + 1][0] = r4[2]; bf[np * 2 + 1][1] = r4[3];
                }
#pragma unroll
                for (int nt = 0; nt < 8; nt++)
                    mma16816(sc[nt], qf[ks], bf[nt]);
            }

            // local max (per-lane over 16 values)
            float mx0 = -1e30f, mx1 = -1e30f;
#pragma unroll
            for (int nt = 0; nt < 8; nt++) {
                mx0 = fmaxf(mx0, fmaxf(sc[nt][0], sc[nt][1]));
                mx1 = fmaxf(mx1, fmaxf(sc[nt][2], sc[nt][3]));
            }

            // warp-vote fast path
            if (__any_sync(0xffffffffu, (mx0 > m0) | (mx1 > m1))) {
                mx0 = fmaxf(mx0, __shfl_xor_sync(0xffffffffu, mx0, 1));
                mx0 = fmaxf(mx0, __shfl_xor_sync(0xffffffffu, mx0, 2));
                mx1 = fmaxf(mx1, __shfl_xor_sync(0xffffffffu, mx1, 1));
                mx1 = fmaxf(mx1, __shfl_xor_sync(0xffffffffu, mx1, 2));
                float nm0 = fmaxf(m0, mx0);
                float nm1 = fmaxf(m1, mx1);
                float cr0 = exp2f(m0 - nm0);
                float cr1 = exp2f(m1 - nm1);
                m0 = nm0;
                m1 = nm1;
                ls[0] *= cr0; ls[1] *= cr0; ls[2] *= cr1; ls[3] *= cr1;
#pragma unroll
                for (int dn = 0; dn < 8; dn++) {
                    of[dn][0] *= cr0; of[dn][1] *= cr0;
                    of[dn][2] *= cr1; of[dn][3] *= cr1;
                }
            }

            // P = exp2(S - m) in fp16x2 (A-fragment layout)
            uint32_t pf[4][4];
#pragma unroll
            for (int kp = 0; kp < 4; kp++) {
                pf[kp][0] = h2exp2(pack_h2(sc[2 * kp][0] - m0,     sc[2 * kp][1] - m0));
                pf[kp][1] = h2exp2(pack_h2(sc[2 * kp][2] - m1,     sc[2 * kp][3] - m1));
                pf[kp][2] = h2exp2(pack_h2(sc[2 * kp + 1][0] - m0, sc[2 * kp + 1][1] - m0));
                pf[kp][3] = h2exp2(pack_h2(sc[2 * kp + 1][2] - m1, sc[2 * kp + 1][3] - m1));
            }

            // row sums via ones-MMA
#pragma unroll
            for (int kp = 0; kp < 4; kp++)
                mma16816(ls, pf[kp], onesb);

            // O += P @ V : x4.trans loads fragment pairs (dn, dn+1)
#pragma unroll
            for (int kp = 0; kp < 4; kp++) {
                uint32_t vf[8][2];
#pragma unroll
                for (int dp = 0; dp < 4; dp++) {
                    int row = kp * 16 + (mat & 1) * 8 + mrow;
                    int col = (dp * 2 + (mat >> 1)) * 8;
                    uint32_t r4[4];
                    ldsm_x4t(r4, sV + (row * 72 + col) * 2);
                    vf[dp * 2][0] = r4[0];     vf[dp * 2][1] = r4[1];
                    vf[dp * 2 + 1][0] = r4[2]; vf[dp * 2 + 1][1] = r4[3];
                }
#pragma unroll
                for (int dn = 0; dn < 8; dn++)
                    mma16816(of[dn], pf[kp], vf[dn]);
            }
        }
    }

    // epilogue
    float inv0 = 1.f / ls[0];
    float inv1 = 1.f / ls[2];
    __half* Ob = O + ((size_t)b * 2048 + q0) * GN + h * 64;
#pragma unroll
    for (int dn = 0; dn < 8; dn++) {
        int col = dn * 8 + qd * 2;
        *reinterpret_cast<uint32_t*>(Ob + (size_t)g * GN + col) =
            pack_h2(of[dn][0] * inv0, of[dn][1] * inv0);
        *reinterpret_cast<uint32_t*>(Ob + (size_t)(g + 8) * GN + col) =
            pack_h2(of[dn][2] * inv1, of[dn][3] * inv1);
    }
}

// ---------------------------------------------------------------------------
extern "C" void kernel_launch(void* const* d_in, const int* in_sizes, int n_in,
                              void* d_out, int out_size)
{
    const float* x   = (const float*)d_in[0];
    const float* ctx = (const float*)d_in[1];
    const float* W0  = (const float*)d_in[2];   // Wq
    const float* b0  = (const float*)d_in[3];
    const float* W1  = (const float*)d_in[4];   // Wks
    const float* b1  = (const float*)d_in[5];
    const float* W2  = (const float*)d_in[6];   // Wvs
    const float* b2  = (const float*)d_in[7];
    const float* W3  = (const float*)d_in[8];   // Wkc
    const float* b3  = (const float*)d_in[9];
    const float* W4  = (const float*)d_in[10];  // Wvc
    const float* b4  = (const float*)d_in[11];
    const float* W5  = (const float*)d_in[12];  // Wo
    const float* b5  = (const float*)d_in[13];
    float* out = (float*)d_out;

    __half* xh;
    __half* ch;
    __half* Wt;
    __half* Qh;
    __half* Kh;
    __half* Vh;
    __half* Oh;
    cudaGetSymbolAddress((void**)&xh, g_xh);
    cudaGetSymbolAddress((void**)&ch, g_ch);
    cudaGetSymbolAddress((void**)&Wt, g_Wt);
    cudaGetSymbolAddress((void**)&Qh, g_Qh);
    cudaGetSymbolAddress((void**)&Kh, g_Kh);
    cudaGetSymbolAddress((void**)&Vh, g_Vh);
    cudaGetSymbolAddress((void**)&Oh, g_Oh);

    // launch 0: fp32 -> fp16 inputs (fused)
    dim3 fgrid(4096, 1, 2);
    f2h2_kernel<<<fgrid, 256>>>(x, ctx, xh, ch, 1048576);

    // launch 1: weights transpose-convert (fused)
    dim3 wgrid(32, 32, 6);
    dim3 wblk(32, 8);
    wtrans6_kernel<<<wgrid, wblk>>>(W0, W1, W2, W3, W4, W5, Wt);

    cudaFuncSetAttribute(hgemm5_kernel,
                         cudaFuncAttributeMaxDynamicSharedMemorySize, SM_GEMM);
    cudaFuncSetAttribute(hgemm_kernel,
                         cudaFuncAttributeMaxDynamicSharedMemorySize, SM_GEMM);
    cudaFuncSetAttribute(attn_hmma_kernel,
                         cudaFuncAttributeMaxDynamicSharedMemorySize, SM_ATTN);

    const float qscale = 0.125f * 1.4426950408889634f;  // 1/sqrt(hd) * log2(e)

    // launch 2: all 5 input projections fused (Q, Ks, Kc, Vs, Vc)
    dim3 ggrid5(8, 32, 5);
    hgemm5_kernel<<<ggrid5, 512, SM_GEMM>>>(xh, ch, Wt, b0, b1, b2, b3, b4,
                                            Qh, Kh, Vh, qscale);

    // launch 3: attention
    dim3 agrid(16, 16, 2);
    attn_hmma_kernel<<<agrid, 256, SM_ATTN>>>(Qh, Kh, Vh, Oh);

    // launch 4: output projection (fp32 out)
    dim3 ggrid(8, 32);
    hgemm_kernel<<<ggrid, 512, SM_GEMM>>>(Oh, Wt + 5u * 1048576u, b5, nullptr, out, 1, 2048, 0, 1.0f);
}

// round 15
// speedup vs baseline: 1.3844x; 1.3844x over previous
#include <cuda_runtime.h>
#include <cuda_fp16.h>
#include <stdint.h>
#include <math.h>

// Shapes: B=2, Tq=2048, Tctx=2048 -> Tk=4096, D=1024, H=16, hd=64
#define GK 1024
#define GN 1024

// ---------------- persistent fp16 scratch ----------------
__device__ __half g_xh[4194304];            // x fp16    [4096][1024]
__device__ __half g_ch[4194304];            // ctx fp16  [4096][1024]
__device__ __half g_Wt[6][1048576];         // W^T fp16  [1024 n][1024 k]
__device__ __half g_Qh[4194304];            // Q (scaled)[2*2048][1024]
__device__ __half g_Kh[8388608];            // K concat  [2*4096][1024]
__device__ __half g_Vh[8388608];            // V concat  [2*4096][1024]
__device__ __half g_Oh[4194304];            // attn out  [2*2048][1024]

// ---------------- ptx helpers ----------------
__device__ __forceinline__ uint32_t smem_u32(const void* p) {
    return static_cast<uint32_t>(__cvta_generic_to_shared(p));
}
__device__ __forceinline__ void cp16(uint32_t dst, const void* src) {
    asm volatile("cp.async.cg.shared.global [%0], [%1], 16;" :: "r"(dst), "l"(src));
}
__device__ __forceinline__ void cp_commit() {
    asm volatile("cp.async.commit_group;" ::: "memory");
}
__device__ __forceinline__ void cp_wait1() {
    asm volatile("cp.async.wait_group 1;" ::: "memory");
}
__device__ __forceinline__ void cp_wait0() {
    asm volatile("cp.async.wait_group 0;" ::: "memory");
}
__device__ __forceinline__ void ldsm_x4(uint32_t* r, uint32_t addr) {
    asm volatile("ldmatrix.sync.aligned.m8n8.x4.shared.b16 {%0,%1,%2,%3}, [%4];"
                 : "=r"(r[0]), "=r"(r[1]), "=r"(r[2]), "=r"(r[3]) : "r"(addr));
}
__device__ __forceinline__ void ldsm_x4t(uint32_t* r, uint32_t addr) {
    asm volatile("ldmatrix.sync.aligned.m8n8.x4.trans.shared.b16 {%0,%1,%2,%3}, [%4];"
                 : "=r"(r[0]), "=r"(r[1]), "=r"(r[2]), "=r"(r[3]) : "r"(addr));
}
__device__ __forceinline__ void mma16816(float* c, const uint32_t* a, const uint32_t* b) {
    asm volatile(
        "mma.sync.aligned.m16n8k16.row.col.f32.f16.f16.f32 "
        "{%0,%1,%2,%3}, {%4,%5,%6,%7}, {%8,%9}, {%0,%1,%2,%3};"
        : "+f"(c[0]), "+f"(c[1]), "+f"(c[2]), "+f"(c[3])
        : "r"(a[0]), "r"(a[1]), "r"(a[2]), "r"(a[3]), "r"(b[0]), "r"(b[1]));
}
__device__ __forceinline__ uint32_t pack_h2(float lo, float hi) {
    __half2 h;
    h.x = __float2half_rn(lo);
    h.y = __float2half_rn(hi);
    uint32_t u;
    memcpy(&u, &h, 4);
    return u;
}
__device__ __forceinline__ uint32_t h2exp2(uint32_t x) {
    uint32_t r;
    asm volatile("ex2.approx.f16x2 %0, %1;" : "=r"(r) : "r"(x));
    return r;
}

// ---------------- fused fp32 -> fp16 convert (z selects tensor) ----------
__global__ void f2h2_kernel(const float* __restrict__ in0, const float* __restrict__ in1,
                            __half* __restrict__ out0, __half* __restrict__ out1, int n4) {
    const float* in = blockIdx.z ? in1 : in0;
    __half* out = blockIdx.z ? out1 : out0;
    int i = blockIdx.x * blockDim.x + threadIdx.x;
    if (i < n4) {
        float4 v = reinterpret_cast<const float4*>(in)[i];
        __half2 a; a.x = __float2half_rn(v.x); a.y = __float2half_rn(v.y);
        __half2 b; b.x = __float2half_rn(v.z); b.y = __float2half_rn(v.w);
        reinterpret_cast<__half2*>(out)[i * 2]     = a;
        reinterpret_cast<__half2*>(out)[i * 2 + 1] = b;
    }
}

// ---------------- fused W [K][N] fp32 -> Wt [N][K] fp16 (z = weight idx) ----
__global__ void wtrans6_kernel(const float* w0, const float* w1, const float* w2,
                               const float* w3, const float* w4, const float* w5,
                               __half* __restrict__ WtBase) {
    __shared__ float t[32][33];
    const float* W;
    switch (blockIdx.z) {
        case 0: W = w0; break;
        case 1: W = w1; break;
        case 2: W = w2; break;
        case 3: W = w3; break;
        case 4: W = w4; break;
        default: W = w5; break;
    }
    __half* Wt = WtBase + (size_t)blockIdx.z * 1048576u;
    int n0 = blockIdx.x * 32, k0 = blockIdx.y * 32;
    int tx = threadIdx.x, ty = threadIdx.y;
#pragma unroll
    for (int i = 0; i < 32; i += 8)
        t[ty + i][tx] = W[(size_t)(k0 + ty + i) * GN + n0 + tx];
    __syncthreads();
#pragma unroll
    for (int i = 0; i < 32; i += 8)
        Wt[(size_t)(n0 + ty + i) * GK + k0 + tx] = __float2half_rn(t[tx][ty + i]);
}

// ---------------- HMMA GEMM, 3-stage cp.async pipeline (R10 proven) --------
// 512 threads, 16 warps (4m x 4n), warp tile 32x32, CTA tile 128x128, BK=32.
#define TSZ 10240
#define A_OFF(s) ((s) * TSZ)
#define B_OFF(s) (3 * TSZ + (s) * TSZ)
#define SM_GEMM (6 * TSZ)

__device__ __forceinline__ void hgemm_body(
    const __half* __restrict__ A, const __half* __restrict__ Bt,
    const float* __restrict__ bias, __half* __restrict__ outH,
    float* __restrict__ outF, int f32out, int bstride, int roff, float scale,
    char* smem)
{
    const uint32_t sb = smem_u32(smem);
    const int tid = threadIdx.x;
    const int lane = tid & 31;
    const int wid = tid >> 5;
    const int wm = (wid >> 2) * 32;
    const int wn = (wid & 3) * 32;
    const int row0 = blockIdx.y * 128;
    const int col0 = blockIdx.x * 128;

    const __half* Ag = A + (size_t)row0 * GK;
    const __half* Bg = Bt + (size_t)col0 * GK;

#define GLOAD(kc, s)                                                         \
    {                                                                        \
        int r = tid >> 2;                                                    \
        int cb = (tid & 3) * 8;                                              \
        cp16(sb + A_OFF(s) + r * 80 + cb * 2,                                \
             Ag + (size_t)r * GK + (kc) * 32 + cb);                          \
        cp16(sb + B_OFF(s) + r * 80 + cb * 2,                                \
             Bg + (size_t)r * GK + (kc) * 32 + cb);                          \
    }

    float acc[2][4][4];
#pragma unroll
    for (int i = 0; i < 2; i++)
#pragma unroll
        for (int j = 0; j < 4; j++)
#pragma unroll
            for (int k = 0; k < 4; k++) acc[i][j][k] = 0.f;

    GLOAD(0, 0); cp_commit();
    GLOAD(1, 1); cp_commit();

    const int mat = lane >> 3;
    const int mrow = lane & 7;

    for (int c = 0; c < 32; c++) {
        const int s = c % 3;
        cp_wait1();
        __syncthreads();
        if (c + 2 < 32) GLOAD(c + 2, (c + 2) % 3);
        cp_commit();

#pragma unroll
        for (int ks = 0; ks < 2; ks++) {
            uint32_t af[2][4];
#pragma unroll
            for (int mt = 0; mt < 2; mt++) {
                int row = wm + mt * 16 + (lane & 7) + (lane & 8);
                int col = ks * 16 + (lane >> 4) * 8;
                ldsm_x4(af[mt], sb + A_OFF(s) + (row * 40 + col) * 2);
            }
            uint32_t bf[4][2];
#pragma unroll
            for (int np = 0; np < 2; np++) {
                int row = wn + (np * 2 + (mat >> 1)) * 8 + mrow;
                int col = ks * 16 + (mat & 1) * 8;
                uint32_t r4[4];
                ldsm_x4(r4, sb + B_OFF(s) + (row * 40 + col) * 2);
                bf[np * 2][0] = r4[0];     bf[np * 2][1] = r4[1];
                bf[np * 2 + 1][0] = r4[2]; bf[np * 2 + 1][1] = r4[3];
            }
#pragma unroll
            for (int mt = 0; mt < 2; mt++)
#pragma unroll
                for (int nt = 0; nt < 4; nt++)
                    mma16816(acc[mt][nt], af[mt], bf[nt]);
        }
    }

    const int g = lane >> 2;
    const int qd = lane & 3;
#pragma unroll
    for (int mt = 0; mt < 2; mt++) {
        int r0 = row0 + wm + mt * 16 + g;
        int r1 = r0 + 8;
        size_t or0 = (size_t)((r0 >> 11) * bstride + (r0 & 2047) + roff);
        size_t or1 = (size_t)((r1 >> 11) * bstride + (r1 & 2047) + roff);
#pragma unroll
        for (int nt = 0; nt < 4; nt++) {
            int col = col0 + wn + nt * 8 + qd * 2;
            float b0 = bias[col];
            float b1 = bias[col + 1];
            float v00 = (acc[mt][nt][0] + b0) * scale;
            float v01 = (acc[mt][nt][1] + b1) * scale;
            float v10 = (acc[mt][nt][2] + b0) * scale;
            float v11 = (acc[mt][nt][3] + b1) * scale;
            if (f32out) {
                outF[or0 * GN + col]     = v00;
                outF[or0 * GN + col + 1] = v01;
                outF[or1 * GN + col]     = v10;
                outF[or1 * GN + col + 1] = v11;
            } else {
                *reinterpret_cast<uint32_t*>(&outH[or0 * GN + col]) = pack_h2(v00, v01);
                *reinterpret_cast<uint32_t*>(&outH[or1 * GN + col]) = pack_h2(v10, v11);
            }
        }
    }
}

__global__ __launch_bounds__(512, 2) void hgemm5_kernel(
    const __half* __restrict__ xh, const __half* __restrict__ ch,
    const __half* __restrict__ WtBase,
    const float* __restrict__ b0, const float* __restrict__ b1,
    const float* __restrict__ b2, const float* __restrict__ b3,
    const float* __restrict__ b4,
    __half* __restrict__ Qh, __half* __restrict__ Kh, __half* __restrict__ Vh,
    float qscale)
{
    extern __shared__ char smem[];
    switch (blockIdx.z) {
        case 0:
            hgemm_body(xh, WtBase + 0u * 1048576u, b0, Qh, nullptr, 0, 2048, 0, qscale, smem);
            break;
        case 1:
            hgemm_body(xh, WtBase + 1u * 1048576u, b1, Kh, nullptr, 0, 4096, 0, 1.0f, smem);
            break;
        case 2:
            hgemm_body(ch, WtBase + 3u * 1048576u, b3, Kh, nullptr, 0, 4096, 2048, 1.0f, smem);
            break;
        case 3:
            hgemm_body(xh, WtBase + 2u * 1048576u, b2, Vh, nullptr, 0, 4096, 0, 1.0f, smem);
            break;
        default:
            hgemm_body(ch, WtBase + 4u * 1048576u, b4, Vh, nullptr, 0, 4096, 2048, 1.0f, smem);
            break;
    }
}

__global__ __launch_bounds__(512, 2) void hgemm_kernel(
    const __half* __restrict__ A, const __half* __restrict__ Bt,
    const float* __restrict__ bias, __half* __restrict__ outH,
    float* __restrict__ outF, int f32out, int bstride, int roff, float scale)
{
    extern __shared__ char smem[];
    hgemm_body(A, Bt, bias, outH, outF, f32out, bstride, roff, scale, smem);
}

// ---------------- flash attention (HMMA) — R10 math, 4-stage ring ----------
// Pair-wise schedule: ONE wait+barrier+commit per 2 iterations, with both
// next-pair loads issued right after the barrier (full 2-kb prefetch window,
// fixing R14's accounting bug). Warps drift up to an iteration apart, so one
// warp's softmax overlaps another's MMAs.
#define KVSTG 18432
#define KOFF(s) ((s) * KVSTG)
#define VOFF(s) ((s) * KVSTG + 9216)
#define SM_ATTN (4 * KVSTG)               // 73728 B

__global__ __launch_bounds__(256, 2) void attn_hmma_kernel(
    const __half* __restrict__ Q, const __half* __restrict__ K,
    const __half* __restrict__ V, __half* __restrict__ O)
{
    extern __shared__ char smem[];
    const uint32_t sb = smem_u32(smem);

    const int tid = threadIdx.x;
    const int lane = tid & 31;
    const int wid = tid >> 5;
    const int qt = blockIdx.x;
    const int h = blockIdx.y;
    const int b = blockIdx.z;
    const int q0 = qt * 128 + wid * 16;
    const int g = lane >> 2;
    const int qd = lane & 3;
    const int mat = lane >> 3;
    const int mrow = lane & 7;

    const __half* Qb = Q + ((size_t)b * 2048 + q0) * GN + h * 64;
    const __half* Kb = K + (size_t)b * 4096 * GN + h * 64;
    const __half* Vb = V + (size_t)b * 4096 * GN + h * 64;

    uint32_t qf[4][4];
#pragma unroll
    for (int ks = 0; ks < 4; ks++) {
        int c0 = ks * 16 + qd * 2;
        qf[ks][0] = *reinterpret_cast<const uint32_t*>(Qb + (size_t)g * GN + c0);
        qf[ks][1] = *reinterpret_cast<const uint32_t*>(Qb + (size_t)(g + 8) * GN + c0);
        qf[ks][2] = *reinterpret_cast<const uint32_t*>(Qb + (size_t)g * GN + c0 + 8);
        qf[ks][3] = *reinterpret_cast<const uint32_t*>(Qb + (size_t)(g + 8) * GN + c0 + 8);
    }

    float of[8][4];
#pragma unroll
    for (int i = 0; i < 8; i++)
#pragma unroll
        for (int j = 0; j < 4; j++) of[i][j] = 0.f;
    float ls[4] = {0.f, 0.f, 0.f, 0.f};
    float m0 = -1e30f, m1 = -1e30f;

    const uint32_t ONES2 = 0x3C003C00u;
    const uint32_t onesb[2] = {ONES2, ONES2};

    const int lr = tid & 63;
    const int lc = (tid >> 6) * 16;

#define LOAD_KV(kb, s)                                                       \
    {                                                                        \
        const __half* Kg = Kb + (size_t)((kb) * 64 + lr) * GN + lc;          \
        const __half* Vg = Vb + (size_t)((kb) * 64 + lr) * GN + lc;          \
        cp16(sb + KOFF(s) + (lr * 72 + lc) * 2, Kg);                         \
        cp16(sb + KOFF(s) + (lr * 72 + lc + 8) * 2, Kg + 8);                 \
        cp16(sb + VOFF(s) + (lr * 72 + lc) * 2, Vg);                         \
        cp16(sb + VOFF(s) + (lr * 72 + lc + 8) * 2, Vg + 8);                 \
    }

    // prologue: stages 0,1 in one group
    LOAD_KV(0, 0);
    LOAD_KV(1, 1);
    cp_commit();

    for (int kb2 = 0; kb2 < 64; kb2 += 2) {
        cp_wait0();          // own copies of stages kb2, kb2+1 complete
        __syncthreads();     // cross-warp visibility + pair p-1 reads done

        // issue BOTH next-pair loads now (one group): full 2-kb window to hide
        if (kb2 + 2 < 64) {
            LOAD_KV(kb2 + 2, (kb2 + 2) & 3);
            LOAD_KV(kb2 + 3, (kb2 + 3) & 3);
        }
        cp_commit();

#pragma unroll
        for (int sub = 0; sub < 2; sub++) {
            const int kb = kb2 + sub;
            const int s = kb & 3;
            const uint32_t sK = sb + KOFF(s);
            const uint32_t sV = sb + VOFF(s);

            // S = Qs @ K^T : x4 loads fragment pairs (nt, nt+1)
            float sc[8][4];
#pragma unroll
            for (int nt = 0; nt < 8; nt++) {
                sc[nt][0] = 0.f; sc[nt][1] = 0.f; sc[nt][2] = 0.f; sc[nt][3] = 0.f;
            }
#pragma unroll
            for (int ks = 0; ks < 4; ks++) {
                uint32_t bf[8][2];
#pragma unroll
                for (int np = 0; np < 4; np++) {
                    int row = (np * 2 + (mat >> 1)) * 8 + mrow;
                    int col = ks * 16 + (mat & 1) * 8;
                    uint32_t r4[4];
                    ldsm_x4(r4, sK + (row * 72 + col) * 2);
                    bf[np * 2][0] = r4[0];     bf[np * 2][1] = r4[1];
                    bf[np * 2 + 1][0] = r4[2]; bf[np * 2 + 1][1] = r4[3];
                }
#pragma unroll
                for (int nt = 0; nt < 8; nt++)
                    mma16816(sc[nt], qf[ks], bf[nt]);
            }

            // local max (per-lane over 16 values)
            float mx0 = -1e30f, mx1 = -1e30f;
#pragma unroll
            for (int nt = 0; nt < 8; nt++) {
                mx0 = fmaxf(mx0, fmaxf(sc[nt][0], sc[nt][1]));
                mx1 = fmaxf(mx1, fmaxf(sc[nt][2], sc[nt][3]));
            }

            // warp-vote fast path
            if (__any_sync(0xffffffffu, (mx0 > m0) | (mx1 > m1))) {
                mx0 = fmaxf(mx0, __shfl_xor_sync(0xffffffffu, mx0, 1));
                mx0 = fmaxf(mx0, __shfl_xor_sync(0xffffffffu, mx0, 2));
                mx1 = fmaxf(mx1, __shfl_xor_sync(0xffffffffu, mx1, 1));
                mx1 = fmaxf(mx1, __shfl_xor_sync(0xffffffffu, mx1, 2));
                float nm0 = fmaxf(m0, mx0);
                float nm1 = fmaxf(m1, mx1);
                float cr0 = exp2f(m0 - nm0);
                float cr1 = exp2f(m1 - nm1);
                m0 = nm0;
                m1 = nm1;
                ls[0] *= cr0; ls[1] *= cr0; ls[2] *= cr1; ls[3] *= cr1;
#pragma unroll
                for (int dn = 0; dn < 8; dn++) {
                    of[dn][0] *= cr0; of[dn][1] *= cr0;
                    of[dn][2] *= cr1; of[dn][3] *= cr1;
                }
            }

            // P = exp2(S - m) in fp16x2 (A-fragment layout)
            uint32_t pf[4][4];
#pragma unroll
            for (int kp = 0; kp < 4; kp++) {
                pf[kp][0] = h2exp2(pack_h2(sc[2 * kp][0] - m0,     sc[2 * kp][1] - m0));
                pf[kp][1] = h2exp2(pack_h2(sc[2 * kp][2] - m1,     sc[2 * kp][3] - m1));
                pf[kp][2] = h2exp2(pack_h2(sc[2 * kp + 1][0] - m0, sc[2 * kp + 1][1] - m0));
                pf[kp][3] = h2exp2(pack_h2(sc[2 * kp + 1][2] - m1, sc[2 * kp + 1][3] - m1));
            }

            // row sums via ones-MMA
#pragma unroll
            for (int kp = 0; kp < 4; kp++)
                mma16816(ls, pf[kp], onesb);

            // O += P @ V : x4.trans loads fragment pairs (dn, dn+1)
#pragma unroll
            for (int kp = 0; kp < 4; kp++) {
                uint32_t vf[8][2];
#pragma unroll
                for (int dp = 0; dp < 4; dp++) {
                    int row = kp * 16 + (mat & 1) * 8 + mrow;
                    int col = (dp * 2 + (mat >> 1)) * 8;
                    uint32_t r4[4];
                    ldsm_x4t(r4, sV + (row * 72 + col) * 2);
                    vf[dp * 2][0] = r4[0];     vf[dp * 2][1] = r4[1];
                    vf[dp * 2 + 1][0] = r4[2]; vf[dp * 2 + 1][1] = r4[3];
                }
#pragma unroll
                for (int dn = 0; dn < 8; dn++)
                    mma16816(of[dn], pf[kp], vf[dn]);
            }
        }
    }

    // epilogue
    float inv0 = 1.f / ls[0];
    float inv1 = 1.f / ls[2];
    __half* Ob = O + ((size_t)b * 2048 + q0) * GN + h * 64;
#pragma unroll
    for (int dn = 0; dn < 8; dn++) {
        int col = dn * 8 + qd * 2;
        *reinterpret_cast<uint32_t*>(Ob + (size_t)g * GN + col) =
            pack_h2(of[dn][0] * inv0, of[dn][1] * inv0);
        *reinterpret_cast<uint32_t*>(Ob + (size_t)(g + 8) * GN + col) =
            pack_h2(of[dn][2] * inv1, of[dn][3] * inv1);
    }
}

// ---------------------------------------------------------------------------
extern "C" void kernel_launch(void* const* d_in, const int* in_sizes, int n_in,
                              void* d_out, int out_size)
{
    const float* x   = (const float*)d_in[0];
    const float* ctx = (const float*)d_in[1];
    const float* W0  = (const float*)d_in[2];   // Wq
    const float* b0  = (const float*)d_in[3];
    const float* W1  = (const float*)d_in[4];   // Wks
    const float* b1  = (const float*)d_in[5];
    const float* W2  = (const float*)d_in[6];   // Wvs
    const float* b2  = (const float*)d_in[7];
    const float* W3  = (const float*)d_in[8];   // Wkc
    const float* b3  = (const float*)d_in[9];
    const float* W4  = (const float*)d_in[10];  // Wvc
    const float* b4  = (const float*)d_in[11];
    const float* W5  = (const float*)d_in[12];  // Wo
    const float* b5  = (const float*)d_in[13];
    float* out = (float*)d_out;

    __half* xh;
    __half* ch;
    __half* Wt;
    __half* Qh;
    __half* Kh;
    __half* Vh;
    __half* Oh;
    cudaGetSymbolAddress((void**)&xh, g_xh);
    cudaGetSymbolAddress((void**)&ch, g_ch);
    cudaGetSymbolAddress((void**)&Wt, g_Wt);
    cudaGetSymbolAddress((void**)&Qh, g_Qh);
    cudaGetSymbolAddress((void**)&Kh, g_Kh);
    cudaGetSymbolAddress((void**)&Vh, g_Vh);
    cudaGetSymbolAddress((void**)&Oh, g_Oh);

    // launch 0: fp32 -> fp16 inputs (fused)
    dim3 fgrid(4096, 1, 2);
    f2h2_kernel<<<fgrid, 256>>>(x, ctx, xh, ch, 1048576);

    // launch 1: weights transpose-convert (fused)
    dim3 wgrid(32, 32, 6);
    dim3 wblk(32, 8);
    wtrans6_kernel<<<wgrid, wblk>>>(W0, W1, W2, W3, W4, W5, Wt);

    cudaFuncSetAttribute(hgemm5_kernel,
                         cudaFuncAttributeMaxDynamicSharedMemorySize, SM_GEMM);
    cudaFuncSetAttribute(hgemm_kernel,
                         cudaFuncAttributeMaxDynamicSharedMemorySize, SM_GEMM);
    cudaFuncSetAttribute(attn_hmma_kernel,
                         cudaFuncAttributeMaxDynamicSharedMemorySize, SM_ATTN);

    const float qscale = 0.125f * 1.4426950408889634f;  // 1/sqrt(hd) * log2(e)

    // launch 2: all 5 input projections fused (Q, Ks, Kc, Vs, Vc)
    dim3 ggrid5(8, 32, 5);
    hgemm5_kernel<<<ggrid5, 512, SM_GEMM>>>(xh, ch, Wt, b0, b1, b2, b3, b4,
                                            Qh, Kh, Vh, qscale);

    // launch 3: attention
    dim3 agrid(16, 16, 2);
    attn_hmma_kernel<<<agrid, 256, SM_ATTN>>>(Qh, Kh, Vh, Oh);

    // launch 4: output projection (fp32 out)
    dim3 ggrid(8, 32);
    hgemm_kernel<<<ggrid, 512, SM_GEMM>>>(Oh, Wt + 5u * 1048576u, b5, nullptr, out, 1, 2048, 0, 1.0f);
}

// round 16
// speedup vs baseline: 1.4382x; 1.0388x over previous
#include <cuda_runtime.h>
#include <cuda_fp16.h>
#include <stdint.h>
#include <math.h>

// Shapes: B=2, Tq=2048, Tctx=2048 -> Tk=4096, D=1024, H=16, hd=64
#define GK 1024
#define GN 1024

// ---------------- persistent fp16 scratch ----------------
__device__ __half g_xh[4194304];            // x fp16    [4096][1024]
__device__ __half g_ch[4194304];            // ctx fp16  [4096][1024]
__device__ __half g_Wt[6][1048576];         // W^T fp16  [1024 n][1024 k]
__device__ __half g_Qh[4194304];            // Q (scaled)[2*2048][1024]
__device__ __half g_Kh[8388608];            // K concat  [2*4096][1024]
__device__ __half g_Vh[8388608];            // V concat  [2*4096][1024]
__device__ __half g_Oh[4194304];            // attn out  [2*2048][1024]

// ---------------- ptx helpers ----------------
__device__ __forceinline__ uint32_t smem_u32(const void* p) {
    return static_cast<uint32_t>(__cvta_generic_to_shared(p));
}
__device__ __forceinline__ void cp16(uint32_t dst, const void* src) {
    asm volatile("cp.async.cg.shared.global [%0], [%1], 16;" :: "r"(dst), "l"(src));
}
__device__ __forceinline__ void cp_commit() {
    asm volatile("cp.async.commit_group;" ::: "memory");
}
__device__ __forceinline__ void cp_wait1() {
    asm volatile("cp.async.wait_group 1;" ::: "memory");
}
__device__ __forceinline__ void ldsm_x4(uint32_t* r, uint32_t addr) {
    asm volatile("ldmatrix.sync.aligned.m8n8.x4.shared.b16 {%0,%1,%2,%3}, [%4];"
                 : "=r"(r[0]), "=r"(r[1]), "=r"(r[2]), "=r"(r[3]) : "r"(addr));
}
__device__ __forceinline__ void ldsm_x4t(uint32_t* r, uint32_t addr) {
    asm volatile("ldmatrix.sync.aligned.m8n8.x4.trans.shared.b16 {%0,%1,%2,%3}, [%4];"
                 : "=r"(r[0]), "=r"(r[1]), "=r"(r[2]), "=r"(r[3]) : "r"(addr));
}
__device__ __forceinline__ void mma16816(float* c, const uint32_t* a, const uint32_t* b) {
    asm volatile(
        "mma.sync.aligned.m16n8k16.row.col.f32.f16.f16.f32 "
        "{%0,%1,%2,%3}, {%4,%5,%6,%7}, {%8,%9}, {%0,%1,%2,%3};"
        : "+f"(c[0]), "+f"(c[1]), "+f"(c[2]), "+f"(c[3])
        : "r"(a[0]), "r"(a[1]), "r"(a[2]), "r"(a[3]), "r"(b[0]), "r"(b[1]));
}
__device__ __forceinline__ uint32_t pack_h2(float lo, float hi) {
    __half2 h;
    h.x = __float2half_rn(lo);
    h.y = __float2half_rn(hi);
    uint32_t u;
    memcpy(&u, &h, 4);
    return u;
}
__device__ __forceinline__ uint32_t h2exp2(uint32_t x) {
    uint32_t r;
    asm volatile("ex2.approx.f16x2 %0, %1;" : "=r"(r) : "r"(x));
    return r;
}

// ---------------- fused fp32 -> fp16 convert (z selects tensor) ----------
__global__ void f2h2_kernel(const float* __restrict__ in0, const float* __restrict__ in1,
                            __half* __restrict__ out0, __half* __restrict__ out1, int n4) {
    const float* in = blockIdx.z ? in1 : in0;
    __half* out = blockIdx.z ? out1 : out0;
    int i = blockIdx.x * blockDim.x + threadIdx.x;
    if (i < n4) {
        float4 v = reinterpret_cast<const float4*>(in)[i];
        __half2 a; a.x = __float2half_rn(v.x); a.y = __float2half_rn(v.y);
        __half2 b; b.x = __float2half_rn(v.z); b.y = __float2half_rn(v.w);
        reinterpret_cast<__half2*>(out)[i * 2]     = a;
        reinterpret_cast<__half2*>(out)[i * 2 + 1] = b;
    }
}

// ---------------- fused W [K][N] fp32 -> Wt [N][K] fp16 (z = weight idx) ----
__global__ void wtrans6_kernel(const float* w0, const float* w1, const float* w2,
                               const float* w3, const float* w4, const float* w5,
                               __half* __restrict__ WtBase) {
    __shared__ float t[32][33];
    const float* W;
    switch (blockIdx.z) {
        case 0: W = w0; break;
        case 1: W = w1; break;
        case 2: W = w2; break;
        case 3: W = w3; break;
        case 4: W = w4; break;
        default: W = w5; break;
    }
    __half* Wt = WtBase + (size_t)blockIdx.z * 1048576u;
    int n0 = blockIdx.x * 32, k0 = blockIdx.y * 32;
    int tx = threadIdx.x, ty = threadIdx.y;
#pragma unroll
    for (int i = 0; i < 32; i += 8)
        t[ty + i][tx] = W[(size_t)(k0 + ty + i) * GN + n0 + tx];
    __syncthreads();
#pragma unroll
    for (int i = 0; i < 32; i += 8)
        Wt[(size_t)(n0 + ty + i) * GK + k0 + tx] = __float2half_rn(t[tx][ty + i]);
}

// ---------------- HMMA GEMM, 3-stage cp.async pipeline (R10 proven) --------
// 512 threads, 16 warps (4m x 4n), warp tile 32x32, CTA tile 128x128, BK=32.
#define TSZ 10240
#define A_OFF(s) ((s) * TSZ)
#define B_OFF(s) (3 * TSZ + (s) * TSZ)
#define SM_GEMM (6 * TSZ)

__device__ __forceinline__ void hgemm_body(
    const __half* __restrict__ A, const __half* __restrict__ Bt,
    const float* __restrict__ bias, __half* __restrict__ outH,
    float* __restrict__ outF, int f32out, int bstride, int roff, float scale,
    char* smem)
{
    const uint32_t sb = smem_u32(smem);
    const int tid = threadIdx.x;
    const int lane = tid & 31;
    const int wid = tid >> 5;
    const int wm = (wid >> 2) * 32;
    const int wn = (wid & 3) * 32;
    const int row0 = blockIdx.y * 128;
    const int col0 = blockIdx.x * 128;

    const __half* Ag = A + (size_t)row0 * GK;
    const __half* Bg = Bt + (size_t)col0 * GK;

#define GLOAD(kc, s)                                                         \
    {                                                                        \
        int r = tid >> 2;                                                    \
        int cb = (tid & 3) * 8;                                              \
        cp16(sb + A_OFF(s) + r * 80 + cb * 2,                                \
             Ag + (size_t)r * GK + (kc) * 32 + cb);                          \
        cp16(sb + B_OFF(s) + r * 80 + cb * 2,                                \
             Bg + (size_t)r * GK + (kc) * 32 + cb);                          \
    }

    float acc[2][4][4];
#pragma unroll
    for (int i = 0; i < 2; i++)
#pragma unroll
        for (int j = 0; j < 4; j++)
#pragma unroll
            for (int k = 0; k < 4; k++) acc[i][j][k] = 0.f;

    GLOAD(0, 0); cp_commit();
    GLOAD(1, 1); cp_commit();

    const int mat = lane >> 3;
    const int mrow = lane & 7;

    for (int c = 0; c < 32; c++) {
        const int s = c % 3;
        cp_wait1();
        __syncthreads();
        if (c + 2 < 32) GLOAD(c + 2, (c + 2) % 3);
        cp_commit();

#pragma unroll
        for (int ks = 0; ks < 2; ks++) {
            uint32_t af[2][4];
#pragma unroll
            for (int mt = 0; mt < 2; mt++) {
                int row = wm + mt * 16 + (lane & 7) + (lane & 8);
                int col = ks * 16 + (lane >> 4) * 8;
                ldsm_x4(af[mt], sb + A_OFF(s) + (row * 40 + col) * 2);
            }
            uint32_t bf[4][2];
#pragma unroll
            for (int np = 0; np < 2; np++) {
                int row = wn + (np * 2 + (mat >> 1)) * 8 + mrow;
                int col = ks * 16 + (mat & 1) * 8;
                uint32_t r4[4];
                ldsm_x4(r4, sb + B_OFF(s) + (row * 40 + col) * 2);
                bf[np * 2][0] = r4[0];     bf[np * 2][1] = r4[1];
                bf[np * 2 + 1][0] = r4[2]; bf[np * 2 + 1][1] = r4[3];
            }
#pragma unroll
            for (int mt = 0; mt < 2; mt++)
#pragma unroll
                for (int nt = 0; nt < 4; nt++)
                    mma16816(acc[mt][nt], af[mt], bf[nt]);
        }
    }

    const int g = lane >> 2;
    const int qd = lane & 3;
#pragma unroll
    for (int mt = 0; mt < 2; mt++) {
        int r0 = row0 + wm + mt * 16 + g;
        int r1 = r0 + 8;
        size_t or0 = (size_t)((r0 >> 11) * bstride + (r0 & 2047) + roff);
        size_t or1 = (size_t)((r1 >> 11) * bstride + (r1 & 2047) + roff);
#pragma unroll
        for (int nt = 0; nt < 4; nt++) {
            int col = col0 + wn + nt * 8 + qd * 2;
            float b0 = bias[col];
            float b1 = bias[col + 1];
            float v00 = (acc[mt][nt][0] + b0) * scale;
            float v01 = (acc[mt][nt][1] + b1) * scale;
            float v10 = (acc[mt][nt][2] + b0) * scale;
            float v11 = (acc[mt][nt][3] + b1) * scale;
            if (f32out) {
                outF[or0 * GN + col]     = v00;
                outF[or0 * GN + col + 1] = v01;
                outF[or1 * GN + col]     = v10;
                outF[or1 * GN + col + 1] = v11;
            } else {
                *reinterpret_cast<uint32_t*>(&outH[or0 * GN + col]) = pack_h2(v00, v01);
                *reinterpret_cast<uint32_t*>(&outH[or1 * GN + col]) = pack_h2(v10, v11);
            }
        }
    }
}

__global__ __launch_bounds__(512, 2) void hgemm5_kernel(
    const __half* __restrict__ xh, const __half* __restrict__ ch,
    const __half* __restrict__ WtBase,
    const float* __restrict__ b0, const float* __restrict__ b1,
    const float* __restrict__ b2, const float* __restrict__ b3,
    const float* __restrict__ b4,
    __half* __restrict__ Qh, __half* __restrict__ Kh, __half* __restrict__ Vh,
    float qscale)
{
    extern __shared__ char smem[];
    switch (blockIdx.z) {
        case 0:
            hgemm_body(xh, WtBase + 0u * 1048576u, b0, Qh, nullptr, 0, 2048, 0, qscale, smem);
            break;
        case 1:
            hgemm_body(xh, WtBase + 1u * 1048576u, b1, Kh, nullptr, 0, 4096, 0, 1.0f, smem);
            break;
        case 2:
            hgemm_body(ch, WtBase + 3u * 1048576u, b3, Kh, nullptr, 0, 4096, 2048, 1.0f, smem);
            break;
        case 3:
            hgemm_body(xh, WtBase + 2u * 1048576u, b2, Vh, nullptr, 0, 4096, 0, 1.0f, smem);
            break;
        default:
            hgemm_body(ch, WtBase + 4u * 1048576u, b4, Vh, nullptr, 0, 4096, 2048, 1.0f, smem);
            break;
    }
}

__global__ __launch_bounds__(512, 2) void hgemm_kernel(
    const __half* __restrict__ A, const __half* __restrict__ Bt,
    const float* __restrict__ bias, __half* __restrict__ outH,
    float* __restrict__ outF, int f32out, int bstride, int roff, float scale)
{
    extern __shared__ char smem[];
    hgemm_body(A, Bt, bias, outH, outF, f32out, bstride, roff, scale, smem);
}

// ---------------- flash attention (HMMA), cross-iteration S/PV pipeline ----
// 4-stage cp.async ring. Per iteration kb: S(kb) MMAs, then PV(kb-1) MMAs
// (tensor work issues back-to-back), then softmax(kb). The softmax serial
// chain hides in the shadow of already-issued tensor work instead of
// blocking PV. Stage usage at iter kb: read K@kb&3 and V@(kb-1)&3, write
// (kb+2)&3 -- all distinct mod 4. Group accounting identical to R10 (wait1).
#define KVSTG 18432
#define KOFF(s) ((s) * KVSTG)
#define VOFF(s) ((s) * KVSTG + 9216)
#define SM_ATTN (4 * KVSTG)               // 73728 B

__global__ __launch_bounds__(256, 2) void attn_hmma_kernel(
    const __half* __restrict__ Q, const __half* __restrict__ K,
    const __half* __restrict__ V, __half* __restrict__ O)
{
    extern __shared__ char smem[];
    const uint32_t sb = smem_u32(smem);

    const int tid = threadIdx.x;
    const int lane = tid & 31;
    const int wid = tid >> 5;
    const int qt = blockIdx.x;
    const int h = blockIdx.y;
    const int b = blockIdx.z;
    const int q0 = qt * 128 + wid * 16;
    const int g = lane >> 2;
    const int qd = lane & 3;
    const int mat = lane >> 3;
    const int mrow = lane & 7;

    const __half* Qb = Q + ((size_t)b * 2048 + q0) * GN + h * 64;
    const __half* Kb = K + (size_t)b * 4096 * GN + h * 64;
    const __half* Vb = V + (size_t)b * 4096 * GN + h * 64;

    uint32_t qf[4][4];
#pragma unroll
    for (int ks = 0; ks < 4; ks++) {
        int c0 = ks * 16 + qd * 2;
        qf[ks][0] = *reinterpret_cast<const uint32_t*>(Qb + (size_t)g * GN + c0);
        qf[ks][1] = *reinterpret_cast<const uint32_t*>(Qb + (size_t)(g + 8) * GN + c0);
        qf[ks][2] = *reinterpret_cast<const uint32_t*>(Qb + (size_t)g * GN + c0 + 8);
        qf[ks][3] = *reinterpret_cast<const uint32_t*>(Qb + (size_t)(g + 8) * GN + c0 + 8);
    }

    float of[8][4];
#pragma unroll
    for (int i = 0; i < 8; i++)
#pragma unroll
        for (int j = 0; j < 4; j++) of[i][j] = 0.f;
    float ls[4] = {0.f, 0.f, 0.f, 0.f};
    float m0 = -1e30f, m1 = -1e30f;

    const uint32_t ONES2 = 0x3C003C00u;
    const uint32_t onesb[2] = {ONES2, ONES2};

    const int lr = tid & 63;
    const int lc = (tid >> 6) * 16;

#define LOAD_KV(kb, s)                                                       \
    {                                                                        \
        const __half* Kg = Kb + (size_t)((kb) * 64 + lr) * GN + lc;          \
        const __half* Vg = Vb + (size_t)((kb) * 64 + lr) * GN + lc;          \
        cp16(sb + KOFF(s) + (lr * 72 + lc) * 2, Kg);                         \
        cp16(sb + KOFF(s) + (lr * 72 + lc + 8) * 2, Kg + 8);                 \
        cp16(sb + VOFF(s) + (lr * 72 + lc) * 2, Vg);                         \
        cp16(sb + VOFF(s) + (lr * 72 + lc + 8) * 2, Vg + 8);                 \
    }

// S-MMA block for stage s into sc (zeroes sc first)
#define DO_S(sK_)                                                            \
    {                                                                        \
        _Pragma("unroll")                                                    \
        for (int nt = 0; nt < 8; nt++) {                                     \
            sc[nt][0] = 0.f; sc[nt][1] = 0.f; sc[nt][2] = 0.f; sc[nt][3] = 0.f; \
        }                                                                    \
        _Pragma("unroll")                                                    \
        for (int ks = 0; ks < 4; ks++) {                                     \
            uint32_t bf[8][2];                                               \
            _Pragma("unroll")                                                \
            for (int np = 0; np < 4; np++) {                                 \
                int row = (np * 2 + (mat >> 1)) * 8 + mrow;                  \
                int col = ks * 16 + (mat & 1) * 8;                           \
                uint32_t r4[4];                                              \
                ldsm_x4(r4, (sK_) + (row * 72 + col) * 2);                   \
                bf[np * 2][0] = r4[0];     bf[np * 2][1] = r4[1];            \
                bf[np * 2 + 1][0] = r4[2]; bf[np * 2 + 1][1] = r4[3];        \
            }                                                                \
            _Pragma("unroll")                                                \
            for (int nt = 0; nt < 8; nt++)                                   \
                mma16816(sc[nt], qf[ks], bf[nt]);                            \
        }                                                                    \
    }

// PV block: ls += pf@ones, of += pf @ V(stage sV_)
#define DO_PV(sV_)                                                           \
    {                                                                        \
        _Pragma("unroll")                                                    \
        for (int kp = 0; kp < 4; kp++)                                       \
            mma16816(ls, pf[kp], onesb);                                     \
        _Pragma("unroll")                                                    \
        for (int kp = 0; kp < 4; kp++) {                                     \
            uint32_t vf[8][2];                                               \
            _Pragma("unroll")                                                \
            for (int dp = 0; dp < 4; dp++) {                                 \
                int row = kp * 16 + (mat & 1) * 8 + mrow;                    \
                int col = (dp * 2 + (mat >> 1)) * 8;                         \
                uint32_t r4[4];                                              \
                ldsm_x4t(r4, (sV_) + (row * 72 + col) * 2);                  \
                vf[dp * 2][0] = r4[0];     vf[dp * 2][1] = r4[1];            \
                vf[dp * 2 + 1][0] = r4[2]; vf[dp * 2 + 1][1] = r4[3];        \
            }                                                                \
            _Pragma("unroll")                                                \
            for (int dn = 0; dn < 8; dn++)                                   \
                mma16816(of[dn], pf[kp], vf[dn]);                            \
        }                                                                    \
    }

// softmax: vote + (maybe) rescale + pf = exp2(sc - m)
#define DO_SOFTMAX()                                                         \
    {                                                                        \
        float mx0 = -1e30f, mx1 = -1e30f;                                    \
        _Pragma("unroll")                                                    \
        for (int nt = 0; nt < 8; nt++) {                                     \
            mx0 = fmaxf(mx0, fmaxf(sc[nt][0], sc[nt][1]));                   \
            mx1 = fmaxf(mx1, fmaxf(sc[nt][2], sc[nt][3]));                   \
        }                                                                    \
        if (__any_sync(0xffffffffu, (mx0 > m0) | (mx1 > m1))) {              \
            mx0 = fmaxf(mx0, __shfl_xor_sync(0xffffffffu, mx0, 1));          \
            mx0 = fmaxf(mx0, __shfl_xor_sync(0xffffffffu, mx0, 2));          \
            mx1 = fmaxf(mx1, __shfl_xor_sync(0xffffffffu, mx1, 1));          \
            mx1 = fmaxf(mx1, __shfl_xor_sync(0xffffffffu, mx1, 2));          \
            float nm0 = fmaxf(m0, mx0);                                      \
            float nm1 = fmaxf(m1, mx1);                                      \
            float cr0 = exp2f(m0 - nm0);                                     \
            float cr1 = exp2f(m1 - nm1);                                     \
            m0 = nm0;                                                        \
            m1 = nm1;                                                        \
            ls[0] *= cr0; ls[1] *= cr0; ls[2] *= cr1; ls[3] *= cr1;          \
            _Pragma("unroll")                                                \
            for (int dn = 0; dn < 8; dn++) {                                 \
                of[dn][0] *= cr0; of[dn][1] *= cr0;                          \
                of[dn][2] *= cr1; of[dn][3] *= cr1;                          \
            }                                                                \
        }                                                                    \
        _Pragma("unroll")                                                    \
        for (int kp = 0; kp < 4; kp++) {                                     \
            pf[kp][0] = h2exp2(pack_h2(sc[2 * kp][0] - m0,     sc[2 * kp][1] - m0)); \
            pf[kp][1] = h2exp2(pack_h2(sc[2 * kp][2] - m1,     sc[2 * kp][3] - m1)); \
            pf[kp][2] = h2exp2(pack_h2(sc[2 * kp + 1][0] - m0, sc[2 * kp + 1][1] - m0)); \
            pf[kp][3] = h2exp2(pack_h2(sc[2 * kp + 1][2] - m1, sc[2 * kp + 1][3] - m1)); \
        }                                                                    \
    }

    float sc[8][4];
    uint32_t pf[4][4];

    // prologue
    LOAD_KV(0, 0); cp_commit();
    LOAD_KV(1, 1); cp_commit();

    // peeled iteration 0: S + softmax only (nothing to PV yet)
    {
        cp_wait1();
        __syncthreads();
        LOAD_KV(2, 2); cp_commit();
        const uint32_t sK = sb + KOFF(0);
        DO_S(sK);
        DO_SOFTMAX();
    }

    for (int kb = 1; kb < 64; kb++) {
        const int s = kb & 3;
        const int sp = (kb - 1) & 3;
        cp_wait1();
        __syncthreads();
        if (kb + 2 < 64) LOAD_KV(kb + 2, (kb + 2) & 3);
        cp_commit();

        const uint32_t sK = sb + KOFF(s);
        const uint32_t sV = sb + VOFF(sp);

        DO_S(sK);        // S(kb) -> sc (pf still holds P(kb-1))
        DO_PV(sV);       // PV(kb-1): tensor work, independent of softmax(kb)
        DO_SOFTMAX();    // softmax(kb) -> m, pf (latency hidden by PV above)
    }

    // tail: PV(63); V(63) lives in stage 3 (loaded at kb=61, never overwritten)
    {
        const uint32_t sV = sb + VOFF(3);
        DO_PV(sV);
    }

    // epilogue
    float inv0 = 1.f / ls[0];
    float inv1 = 1.f / ls[2];
    __half* Ob = O + ((size_t)b * 2048 + q0) * GN + h * 64;
#pragma unroll
    for (int dn = 0; dn < 8; dn++) {
        int col = dn * 8 + qd * 2;
        *reinterpret_cast<uint32_t*>(Ob + (size_t)g * GN + col) =
            pack_h2(of[dn][0] * inv0, of[dn][1] * inv0);
        *reinterpret_cast<uint32_t*>(Ob + (size_t)(g + 8) * GN + col) =
            pack_h2(of[dn][2] * inv1, of[dn][3] * inv1);
    }
}

// ---------------------------------------------------------------------------
extern "C" void kernel_launch(void* const* d_in, const int* in_sizes, int n_in,
                              void* d_out, int out_size)
{
    const float* x   = (const float*)d_in[0];
    const float* ctx = (const float*)d_in[1];
    const float* W0  = (const float*)d_in[2];   // Wq
    const float* b0  = (const float*)d_in[3];
    const float* W1  = (const float*)d_in[4];   // Wks
    const float* b1  = (const float*)d_in[5];
    const float* W2  = (const float*)d_in[6];   // Wvs
    const float* b2  = (const float*)d_in[7];
    const float* W3  = (const float*)d_in[8];   // Wkc
    const float* b3  = (const float*)d_in[9];
    const float* W4  = (const float*)d_in[10];  // Wvc
    const float* b4  = (const float*)d_in[11];
    const float* W5  = (const float*)d_in[12];  // Wo
    const float* b5  = (const float*)d_in[13];
    float* out = (float*)d_out;

    __half* xh;
    __half* ch;
    __half* Wt;
    __half* Qh;
    __half* Kh;
    __half* Vh;
    __half* Oh;
    cudaGetSymbolAddress((void**)&xh, g_xh);
    cudaGetSymbolAddress((void**)&ch, g_ch);
    cudaGetSymbolAddress((void**)&Wt, g_Wt);
    cudaGetSymbolAddress((void**)&Qh, g_Qh);
    cudaGetSymbolAddress((void**)&Kh, g_Kh);
    cudaGetSymbolAddress((void**)&Vh, g_Vh);
    cudaGetSymbolAddress((void**)&Oh, g_Oh);

    // launch 0: fp32 -> fp16 inputs (fused)
    dim3 fgrid(4096, 1, 2);
    f2h2_kernel<<<fgrid, 256>>>(x, ctx, xh, ch, 1048576);

    // launch 1: weights transpose-convert (fused)
    dim3 wgrid(32, 32, 6);
    dim3 wblk(32, 8);
    wtrans6_kernel<<<wgrid, wblk>>>(W0, W1, W2, W3, W4, W5, Wt);

    cudaFuncSetAttribute(hgemm5_kernel,
                         cudaFuncAttributeMaxDynamicSharedMemorySize, SM_GEMM);
    cudaFuncSetAttribute(hgemm_kernel,
                         cudaFuncAttributeMaxDynamicSharedMemorySize, SM_GEMM);
    cudaFuncSetAttribute(attn_hmma_kernel,
                         cudaFuncAttributeMaxDynamicSharedMemorySize, SM_ATTN);

    const float qscale = 0.125f * 1.4426950408889634f;  // 1/sqrt(hd) * log2(e)

    // launch 2: all 5 input projections fused (Q, Ks, Kc, Vs, Vc)
    dim3 ggrid5(8, 32, 5);
    hgemm5_kernel<<<ggrid5, 512, SM_GEMM>>>(xh, ch, Wt, b0, b1, b2, b3, b4,
                                            Qh, Kh, Vh, qscale);

    // launch 3: attention
    dim3 agrid(16, 16, 2);
    attn_hmma_kernel<<<agrid, 256, SM_ATTN>>>(Qh, Kh, Vh, Oh);

    // launch 4: output projection (fp32 out)
    dim3 ggrid(8, 32);
    hgemm_kernel<<<ggrid, 512, SM_GEMM>>>(Oh, Wt + 5u * 1048576u, b5, nullptr, out, 1, 2048, 0, 1.0f);
}

// round 17
// speedup vs baseline: 1.4692x; 1.0216x over previous
#include <cuda_runtime.h>
#include <cuda_fp16.h>
#include <stdint.h>
#include <math.h>

// Shapes: B=2, Tq=2048, Tctx=2048 -> Tk=4096, D=1024, H=16, hd=64
#define GK 1024
#define GN 1024

// ---------------- persistent fp16 scratch ----------------
__device__ __half g_xh[4194304];            // x fp16    [4096][1024]
__device__ __half g_ch[4194304];            // ctx fp16  [4096][1024]
__device__ __half g_Wt[6][1048576];         // W^T fp16  [1024 n][1024 k]
__device__ __half g_Qh[4194304];            // Q (scaled)[2*2048][1024]
__device__ __half g_Kh[8388608];            // K concat  [2*4096][1024]
__device__ __half g_Vh[8388608];            // V concat  [2*4096][1024]
__device__ __half g_Oh[4194304];            // attn out  [2*2048][1024]

// ---------------- ptx helpers ----------------
__device__ __forceinline__ uint32_t smem_u32(const void* p) {
    return static_cast<uint32_t>(__cvta_generic_to_shared(p));
}
__device__ __forceinline__ void cp16(uint32_t dst, const void* src) {
    asm volatile("cp.async.cg.shared.global [%0], [%1], 16;" :: "r"(dst), "l"(src));
}
__device__ __forceinline__ void cp_commit() {
    asm volatile("cp.async.commit_group;" ::: "memory");
}
__device__ __forceinline__ void cp_wait1() {
    asm volatile("cp.async.wait_group 1;" ::: "memory");
}
__device__ __forceinline__ void cp_wait0() {
    asm volatile("cp.async.wait_group 0;" ::: "memory");
}
__device__ __forceinline__ void ldsm_x4(uint32_t* r, uint32_t addr) {
    asm volatile("ldmatrix.sync.aligned.m8n8.x4.shared.b16 {%0,%1,%2,%3}, [%4];"
                 : "=r"(r[0]), "=r"(r[1]), "=r"(r[2]), "=r"(r[3]) : "r"(addr));
}
__device__ __forceinline__ void ldsm_x4t(uint32_t* r, uint32_t addr) {
    asm volatile("ldmatrix.sync.aligned.m8n8.x4.trans.shared.b16 {%0,%1,%2,%3}, [%4];"
                 : "=r"(r[0]), "=r"(r[1]), "=r"(r[2]), "=r"(r[3]) : "r"(addr));
}
__device__ __forceinline__ void mma16816(float* c, const uint32_t* a, const uint32_t* b) {
    asm volatile(
        "mma.sync.aligned.m16n8k16.row.col.f32.f16.f16.f32 "
        "{%0,%1,%2,%3}, {%4,%5,%6,%7}, {%8,%9}, {%0,%1,%2,%3};"
        : "+f"(c[0]), "+f"(c[1]), "+f"(c[2]), "+f"(c[3])
        : "r"(a[0]), "r"(a[1]), "r"(a[2]), "r"(a[3]), "r"(b[0]), "r"(b[1]));
}
__device__ __forceinline__ uint32_t pack_h2(float lo, float hi) {
    __half2 h;
    h.x = __float2half_rn(lo);
    h.y = __float2half_rn(hi);
    uint32_t u;
    memcpy(&u, &h, 4);
    return u;
}
__device__ __forceinline__ uint32_t h2exp2(uint32_t x) {
    uint32_t r;
    asm volatile("ex2.approx.f16x2 %0, %1;" : "=r"(r) : "r"(x));
    return r;
}

// ---------------- fused fp32 -> fp16 convert (z selects tensor) ----------
__global__ void f2h2_kernel(const float* __restrict__ in0, const float* __restrict__ in1,
                            __half* __restrict__ out0, __half* __restrict__ out1, int n4) {
    const float* in = blockIdx.z ? in1 : in0;
    __half* out = blockIdx.z ? out1 : out0;
    int i = blockIdx.x * blockDim.x + threadIdx.x;
    if (i < n4) {
        float4 v = reinterpret_cast<const float4*>(in)[i];
        __half2 a; a.x = __float2half_rn(v.x); a.y = __float2half_rn(v.y);
        __half2 b; b.x = __float2half_rn(v.z); b.y = __float2half_rn(v.w);
        reinterpret_cast<__half2*>(out)[i * 2]     = a;
        reinterpret_cast<__half2*>(out)[i * 2 + 1] = b;
    }
}

// ---------------- fused W [K][N] fp32 -> Wt [N][K] fp16 (z = weight idx) ----
__global__ void wtrans6_kernel(const float* w0, const float* w1, const float* w2,
                               const float* w3, const float* w4, const float* w5,
                               __half* __restrict__ WtBase) {
    __shared__ float t[32][33];
    const float* W;
    switch (blockIdx.z) {
        case 0: W = w0; break;
        case 1: W = w1; break;
        case 2: W = w2; break;
        case 3: W = w3; break;
        case 4: W = w4; break;
        default: W = w5; break;
    }
    __half* Wt = WtBase + (size_t)blockIdx.z * 1048576u;
    int n0 = blockIdx.x * 32, k0 = blockIdx.y * 32;
    int tx = threadIdx.x, ty = threadIdx.y;
#pragma unroll
    for (int i = 0; i < 32; i += 8)
        t[ty + i][tx] = W[(size_t)(k0 + ty + i) * GN + n0 + tx];
    __syncthreads();
#pragma unroll
    for (int i = 0; i < 32; i += 8)
        Wt[(size_t)(n0 + ty + i) * GK + k0 + tx] = __float2half_rn(t[tx][ty + i]);
}

// ---------------- HMMA GEMM, 3-stage cp.async pipeline (R10 proven) --------
// 512 threads, 16 warps (4m x 4n), warp tile 32x32, CTA tile 128x128, BK=32.
#define TSZ 10240
#define A_OFF(s) ((s) * TSZ)
#define B_OFF(s) (3 * TSZ + (s) * TSZ)
#define SM_GEMM (6 * TSZ)

__device__ __forceinline__ void hgemm_body(
    const __half* __restrict__ A, const __half* __restrict__ Bt,
    const float* __restrict__ bias, __half* __restrict__ outH,
    float* __restrict__ outF, int f32out, int bstride, int roff, float scale,
    char* smem)
{
    const uint32_t sb = smem_u32(smem);
    const int tid = threadIdx.x;
    const int lane = tid & 31;
    const int wid = tid >> 5;
    const int wm = (wid >> 2) * 32;
    const int wn = (wid & 3) * 32;
    const int row0 = blockIdx.y * 128;
    const int col0 = blockIdx.x * 128;

    const __half* Ag = A + (size_t)row0 * GK;
    const __half* Bg = Bt + (size_t)col0 * GK;

#define GLOAD(kc, s)                                                         \
    {                                                                        \
        int r = tid >> 2;                                                    \
        int cb = (tid & 3) * 8;                                              \
        cp16(sb + A_OFF(s) + r * 80 + cb * 2,                                \
             Ag + (size_t)r * GK + (kc) * 32 + cb);                          \
        cp16(sb + B_OFF(s) + r * 80 + cb * 2,                                \
             Bg + (size_t)r * GK + (kc) * 32 + cb);                          \
    }

    float acc[2][4][4];
#pragma unroll
    for (int i = 0; i < 2; i++)
#pragma unroll
        for (int j = 0; j < 4; j++)
#pragma unroll
            for (int k = 0; k < 4; k++) acc[i][j][k] = 0.f;

    GLOAD(0, 0); cp_commit();
    GLOAD(1, 1); cp_commit();

    const int mat = lane >> 3;
    const int mrow = lane & 7;

    for (int c = 0; c < 32; c++) {
        const int s = c % 3;
        cp_wait1();
        __syncthreads();
        if (c + 2 < 32) GLOAD(c + 2, (c + 2) % 3);
        cp_commit();

#pragma unroll
        for (int ks = 0; ks < 2; ks++) {
            uint32_t af[2][4];
#pragma unroll
            for (int mt = 0; mt < 2; mt++) {
                int row = wm + mt * 16 + (lane & 7) + (lane & 8);
                int col = ks * 16 + (lane >> 4) * 8;
                ldsm_x4(af[mt], sb + A_OFF(s) + (row * 40 + col) * 2);
            }
            uint32_t bf[4][2];
#pragma unroll
            for (int np = 0; np < 2; np++) {
                int row = wn + (np * 2 + (mat >> 1)) * 8 + mrow;
                int col = ks * 16 + (mat & 1) * 8;
                uint32_t r4[4];
                ldsm_x4(r4, sb + B_OFF(s) + (row * 40 + col) * 2);
                bf[np * 2][0] = r4[0];     bf[np * 2][1] = r4[1];
                bf[np * 2 + 1][0] = r4[2]; bf[np * 2 + 1][1] = r4[3];
            }
#pragma unroll
            for (int mt = 0; mt < 2; mt++)
#pragma unroll
                for (int nt = 0; nt < 4; nt++)
                    mma16816(acc[mt][nt], af[mt], bf[nt]);
        }
    }

    const int g = lane >> 2;
    const int qd = lane & 3;
#pragma unroll
    for (int mt = 0; mt < 2; mt++) {
        int r0 = row0 + wm + mt * 16 + g;
        int r1 = r0 + 8;
        size_t or0 = (size_t)((r0 >> 11) * bstride + (r0 & 2047) + roff);
        size_t or1 = (size_t)((r1 >> 11) * bstride + (r1 & 2047) + roff);
#pragma unroll
        for (int nt = 0; nt < 4; nt++) {
            int col = col0 + wn + nt * 8 + qd * 2;
            float b0 = bias[col];
            float b1 = bias[col + 1];
            float v00 = (acc[mt][nt][0] + b0) * scale;
            float v01 = (acc[mt][nt][1] + b1) * scale;
            float v10 = (acc[mt][nt][2] + b0) * scale;
            float v11 = (acc[mt][nt][3] + b1) * scale;
            if (f32out) {
                outF[or0 * GN + col]     = v00;
                outF[or0 * GN + col + 1] = v01;
                outF[or1 * GN + col]     = v10;
                outF[or1 * GN + col + 1] = v11;
            } else {
                *reinterpret_cast<uint32_t*>(&outH[or0 * GN + col]) = pack_h2(v00, v01);
                *reinterpret_cast<uint32_t*>(&outH[or1 * GN + col]) = pack_h2(v10, v11);
            }
        }
    }
}

__global__ __launch_bounds__(512, 2) void hgemm5_kernel(
    const __half* __restrict__ xh, const __half* __restrict__ ch,
    const __half* __restrict__ WtBase,
    const float* __restrict__ b0, const float* __restrict__ b1,
    const float* __restrict__ b2, const float* __restrict__ b3,
    const float* __restrict__ b4,
    __half* __restrict__ Qh, __half* __restrict__ Kh, __half* __restrict__ Vh,
    float qscale)
{
    extern __shared__ char smem[];
    switch (blockIdx.z) {
        case 0:
            hgemm_body(xh, WtBase + 0u * 1048576u, b0, Qh, nullptr, 0, 2048, 0, qscale, smem);
            break;
        case 1:
            hgemm_body(xh, WtBase + 1u * 1048576u, b1, Kh, nullptr, 0, 4096, 0, 1.0f, smem);
            break;
        case 2:
            hgemm_body(ch, WtBase + 3u * 1048576u, b3, Kh, nullptr, 0, 4096, 2048, 1.0f, smem);
            break;
        case 3:
            hgemm_body(xh, WtBase + 2u * 1048576u, b2, Vh, nullptr, 0, 4096, 0, 1.0f, smem);
            break;
        default:
            hgemm_body(ch, WtBase + 4u * 1048576u, b4, Vh, nullptr, 0, 4096, 2048, 1.0f, smem);
            break;
    }
}

__global__ __launch_bounds__(512, 2) void hgemm_kernel(
    const __half* __restrict__ A, const __half* __restrict__ Bt,
    const float* __restrict__ bias, __half* __restrict__ outH,
    float* __restrict__ outF, int f32out, int bstride, int roff, float scale)
{
    extern __shared__ char smem[];
    hgemm_body(A, Bt, bias, outH, outF, f32out, bstride, roff, scale, smem);
}

// ---------------- flash attention (HMMA), S/PV pipeline + paired barriers ---
// 5-stage cp.async ring, ONE wait0+barrier per 2 iterations. Per pair
// (kb2, kb2+1): S(kb2), PV(kb2-1), softmax(kb2), [load kb2+2,kb2+3 as one
// group], S(kb2+1), PV(kb2), softmax(kb2+1). Reads span stages
// {kb2-1,kb2,kb2+1}, writes {kb2+2,kb2+3} -- 5 consecutive, distinct mod 5;
// writes are after the pair barrier which fences the previous pair's reads.
#define KVSTG 18432
#define KOFF(s) ((s) * KVSTG)
#define VOFF(s) ((s) * KVSTG + 9216)
#define SM_ATTN (5 * KVSTG)               // 92160 B

__global__ __launch_bounds__(256, 2) void attn_hmma_kernel(
    const __half* __restrict__ Q, const __half* __restrict__ K,
    const __half* __restrict__ V, __half* __restrict__ O)
{
    extern __shared__ char smem[];
    const uint32_t sb = smem_u32(smem);

    const int tid = threadIdx.x;
    const int lane = tid & 31;
    const int wid = tid >> 5;
    const int qt = blockIdx.x;
    const int h = blockIdx.y;
    const int b = blockIdx.z;
    const int q0 = qt * 128 + wid * 16;
    const int g = lane >> 2;
    const int qd = lane & 3;
    const int mat = lane >> 3;
    const int mrow = lane & 7;

    const __half* Qb = Q + ((size_t)b * 2048 + q0) * GN + h * 64;
    const __half* Kb = K + (size_t)b * 4096 * GN + h * 64;
    const __half* Vb = V + (size_t)b * 4096 * GN + h * 64;

    uint32_t qf[4][4];
#pragma unroll
    for (int ks = 0; ks < 4; ks++) {
        int c0 = ks * 16 + qd * 2;
        qf[ks][0] = *reinterpret_cast<const uint32_t*>(Qb + (size_t)g * GN + c0);
        qf[ks][1] = *reinterpret_cast<const uint32_t*>(Qb + (size_t)(g + 8) * GN + c0);
        qf[ks][2] = *reinterpret_cast<const uint32_t*>(Qb + (size_t)g * GN + c0 + 8);
        qf[ks][3] = *reinterpret_cast<const uint32_t*>(Qb + (size_t)(g + 8) * GN + c0 + 8);
    }

    float of[8][4];
#pragma unroll
    for (int i = 0; i < 8; i++)
#pragma unroll
        for (int j = 0; j < 4; j++) of[i][j] = 0.f;
    float ls[4] = {0.f, 0.f, 0.f, 0.f};
    float m0 = -1e30f, m1 = -1e30f;

    const uint32_t ONES2 = 0x3C003C00u;
    const uint32_t onesb[2] = {ONES2, ONES2};

    const int lr = tid & 63;
    const int lc = (tid >> 6) * 16;

#define LOAD_KV(kb, s)                                                       \
    {                                                                        \
        const __half* Kg = Kb + (size_t)((kb) * 64 + lr) * GN + lc;          \
        const __half* Vg = Vb + (size_t)((kb) * 64 + lr) * GN + lc;          \
        cp16(sb + KOFF(s) + (lr * 72 + lc) * 2, Kg);                         \
        cp16(sb + KOFF(s) + (lr * 72 + lc + 8) * 2, Kg + 8);                 \
        cp16(sb + VOFF(s) + (lr * 72 + lc) * 2, Vg);                         \
        cp16(sb + VOFF(s) + (lr * 72 + lc + 8) * 2, Vg + 8);                 \
    }

#define DO_S(sK_)                                                            \
    {                                                                        \
        _Pragma("unroll")                                                    \
        for (int nt = 0; nt < 8; nt++) {                                     \
            sc[nt][0] = 0.f; sc[nt][1] = 0.f; sc[nt][2] = 0.f; sc[nt][3] = 0.f; \
        }                                                                    \
        _Pragma("unroll")                                                    \
        for (int ks = 0; ks < 4; ks++) {                                     \
            uint32_t bf[8][2];                                               \
            _Pragma("unroll")                                                \
            for (int np = 0; np < 4; np++) {                                 \
                int row = (np * 2 + (mat >> 1)) * 8 + mrow;                  \
                int col = ks * 16 + (mat & 1) * 8;                           \
                uint32_t r4[4];                                              \
                ldsm_x4(r4, (sK_) + (row * 72 + col) * 2);                   \
                bf[np * 2][0] = r4[0];     bf[np * 2][1] = r4[1];            \
                bf[np * 2 + 1][0] = r4[2]; bf[np * 2 + 1][1] = r4[3];        \
            }                                                                \
            _Pragma("unroll")                                                \
            for (int nt = 0; nt < 8; nt++)                                   \
                mma16816(sc[nt], qf[ks], bf[nt]);                            \
        }                                                                    \
    }

#define DO_PV(sV_)                                                           \
    {                                                                        \
        _Pragma("unroll")                                                    \
        for (int kp = 0; kp < 4; kp++)                                       \
            mma16816(ls, pf[kp], onesb);                                     \
        _Pragma("unroll")                                                    \
        for (int kp = 0; kp < 4; kp++) {                                     \
            uint32_t vf[8][2];                                               \
            _Pragma("unroll")                                                \
            for (int dp = 0; dp < 4; dp++) {                                 \
                int row = kp * 16 + (mat & 1) * 8 + mrow;                    \
                int col = (dp * 2 + (mat >> 1)) * 8;                         \
                uint32_t r4[4];                                              \
                ldsm_x4t(r4, (sV_) + (row * 72 + col) * 2);                  \
                vf[dp * 2][0] = r4[0];     vf[dp * 2][1] = r4[1];            \
                vf[dp * 2 + 1][0] = r4[2]; vf[dp * 2 + 1][1] = r4[3];        \
            }                                                                \
            _Pragma("unroll")                                                \
            for (int dn = 0; dn < 8; dn++)                                   \
                mma16816(of[dn], pf[kp], vf[dn]);                            \
        }                                                                    \
    }

#define DO_SOFTMAX()                                                         \
    {                                                                        \
        float mx0 = -1e30f, mx1 = -1e30f;                                    \
        _Pragma("unroll")                                                    \
        for (int nt = 0; nt < 8; nt++) {                                     \
            mx0 = fmaxf(mx0, fmaxf(sc[nt][0], sc[nt][1]));                   \
            mx1 = fmaxf(mx1, fmaxf(sc[nt][2], sc[nt][3]));                   \
        }                                                                    \
        if (__any_sync(0xffffffffu, (mx0 > m0) | (mx1 > m1))) {              \
            mx0 = fmaxf(mx0, __shfl_xor_sync(0xffffffffu, mx0, 1));          \
            mx0 = fmaxf(mx0, __shfl_xor_sync(0xffffffffu, mx0, 2));          \
            mx1 = fmaxf(mx1, __shfl_xor_sync(0xffffffffu, mx1, 1));          \
            mx1 = fmaxf(mx1, __shfl_xor_sync(0xffffffffu, mx1, 2));          \
            float nm0 = fmaxf(m0, mx0);                                      \
            float nm1 = fmaxf(m1, mx1);                                      \
            float cr0 = exp2f(m0 - nm0);                                     \
            float cr1 = exp2f(m1 - nm1);                                     \
            m0 = nm0;                                                        \
            m1 = nm1;                                                        \
            ls[0] *= cr0; ls[1] *= cr0; ls[2] *= cr1; ls[3] *= cr1;          \
            _Pragma("unroll")                                                \
            for (int dn = 0; dn < 8; dn++) {                                 \
                of[dn][0] *= cr0; of[dn][1] *= cr0;                          \
                of[dn][2] *= cr1; of[dn][3] *= cr1;                          \
            }                                                                \
        }                                                                    \
        _Pragma("unroll")                                                    \
        for (int kp = 0; kp < 4; kp++) {                                     \
            pf[kp][0] = h2exp2(pack_h2(sc[2 * kp][0] - m0,     sc[2 * kp][1] - m0)); \
            pf[kp][1] = h2exp2(pack_h2(sc[2 * kp][2] - m1,     sc[2 * kp][3] - m1)); \
            pf[kp][2] = h2exp2(pack_h2(sc[2 * kp + 1][0] - m0, sc[2 * kp + 1][1] - m0)); \
            pf[kp][3] = h2exp2(pack_h2(sc[2 * kp + 1][2] - m1, sc[2 * kp + 1][3] - m1)); \
        }                                                                    \
    }

    float sc[8][4];
    uint32_t pf[4][4];

    // prologue: stages 0,1 (kb 0,1) as ONE group
    LOAD_KV(0, 0);
    LOAD_KV(1, 1);
    cp_commit();

    // pair 0 (peeled: kb=0 has no PV)
    cp_wait0();
    __syncthreads();
    {
        const uint32_t sK = sb + KOFF(0);
        DO_S(sK);
        DO_SOFTMAX();
    }
    LOAD_KV(2, 2);
    LOAD_KV(3, 3);
    cp_commit();
    {
        const uint32_t sK = sb + KOFF(1);
        const uint32_t sV = sb + VOFF(0);
        DO_S(sK);
        DO_PV(sV);
        DO_SOFTMAX();
    }

    for (int kb2 = 2; kb2 < 64; kb2 += 2) {
        cp_wait0();
        __syncthreads();
        {
            const int s  = kb2 % 5;
            const int sp = (kb2 - 1) % 5;
            const uint32_t sK = sb + KOFF(s);
            const uint32_t sV = sb + VOFF(sp);
            DO_S(sK);
            DO_PV(sV);
            DO_SOFTMAX();
        }
        if (kb2 + 2 < 64) {
            LOAD_KV(kb2 + 2, (kb2 + 2) % 5);
            LOAD_KV(kb2 + 3, (kb2 + 3) % 5);
            cp_commit();
        }
        {
            const int s  = (kb2 + 1) % 5;
            const int sp = kb2 % 5;
            const uint32_t sK = sb + KOFF(s);
            const uint32_t sV = sb + VOFF(sp);
            DO_S(sK);
            DO_PV(sV);
            DO_SOFTMAX();
        }
    }

    // tail: PV(63), V lives in stage 63 % 5 = 3
    {
        const uint32_t sV = sb + VOFF(3);
        DO_PV(sV);
    }

    // epilogue
    float inv0 = 1.f / ls[0];
    float inv1 = 1.f / ls[2];
    __half* Ob = O + ((size_t)b * 2048 + q0) * GN + h * 64;
#pragma unroll
    for (int dn = 0; dn < 8; dn++) {
        int col = dn * 8 + qd * 2;
        *reinterpret_cast<uint32_t*>(Ob + (size_t)g * GN + col) =
            pack_h2(of[dn][0] * inv0, of[dn][1] * inv0);
        *reinterpret_cast<uint32_t*>(Ob + (size_t)(g + 8) * GN + col) =
            pack_h2(of[dn][2] * inv1, of[dn][3] * inv1);
    }
}

// ---------------------------------------------------------------------------
extern "C" void kernel_launch(void* const* d_in, const int* in_sizes, int n_in,
                              void* d_out, int out_size)
{
    const float* x   = (const float*)d_in[0];
    const float* ctx = (const float*)d_in[1];
    const float* W0  = (const float*)d_in[2];   // Wq
    const float* b0  = (const float*)d_in[3];
    const float* W1  = (const float*)d_in[4];   // Wks
    const float* b1  = (const float*)d_in[5];
    const float* W2  = (const float*)d_in[6];   // Wvs
    const float* b2  = (const float*)d_in[7];
    const float* W3  = (const float*)d_in[8];   // Wkc
    const float* b3  = (const float*)d_in[9];
    const float* W4  = (const float*)d_in[10];  // Wvc
    const float* b4  = (const float*)d_in[11];
    const float* W5  = (const float*)d_in[12];  // Wo
    const float* b5  = (const float*)d_in[13];
    float* out = (float*)d_out;

    __half* xh;
    __half* ch;
    __half* Wt;
    __half* Qh;
    __half* Kh;
    __half* Vh;
    __half* Oh;
    cudaGetSymbolAddress((void**)&xh, g_xh);
    cudaGetSymbolAddress((void**)&ch, g_ch);
    cudaGetSymbolAddress((void**)&Wt, g_Wt);
    cudaGetSymbolAddress((void**)&Qh, g_Qh);
    cudaGetSymbolAddress((void**)&Kh, g_Kh);
    cudaGetSymbolAddress((void**)&Vh, g_Vh);
    cudaGetSymbolAddress((void**)&Oh, g_Oh);

    // launch 0: fp32 -> fp16 inputs (fused)
    dim3 fgrid(4096, 1, 2);
    f2h2_kernel<<<fgrid, 256>>>(x, ctx, xh, ch, 1048576);

    // launch 1: weights transpose-convert (fused)
    dim3 wgrid(32, 32, 6);
    dim3 wblk(32, 8);
    wtrans6_kernel<<<wgrid, wblk>>>(W0, W1, W2, W3, W4, W5, Wt);

    cudaFuncSetAttribute(hgemm5_kernel,
                         cudaFuncAttributeMaxDynamicSharedMemorySize, SM_GEMM);
    cudaFuncSetAttribute(hgemm_kernel,
                         cudaFuncAttributeMaxDynamicSharedMemorySize, SM_GEMM);
    cudaFuncSetAttribute(attn_hmma_kernel,
                         cudaFuncAttributeMaxDynamicSharedMemorySize, SM_ATTN);

    const float qscale = 0.125f * 1.4426950408889634f;  // 1/sqrt(hd) * log2(e)

    // launch 2: all 5 input projections fused (Q, Ks, Kc, Vs, Vc)
    dim3 ggrid5(8, 32, 5);
    hgemm5_kernel<<<ggrid5, 512, SM_GEMM>>>(xh, ch, Wt, b0, b1, b2, b3, b4,
                                            Qh, Kh, Vh, qscale);

    // launch 3: attention
    dim3 agrid(16, 16, 2);
    attn_hmma_kernel<<<agrid, 256, SM_ATTN>>>(Qh, Kh, Vh, Oh);

    // launch 4: output projection (fp32 out)
    dim3 ggrid(8, 32);
    hgemm_kernel<<<ggrid, 512, SM_GEMM>>>(Oh, Wt + 5u * 1048576u, b5, nullptr, out, 1, 2048, 0, 1.0f);
}